// round 17
// baseline (speedup 1.0000x reference)
#include <cuda_runtime.h>
#include <cuda_fp16.h>
#include <cstdint>

#define B_  1024
#define D_  512
#define V_  100000

constexpr float MARGIN_COS = 0.9210609940028851f;  // cos(0.4)
constexpr float MARGIN_SIN = 0.3894183423086505f;  // sin(0.4)
constexpr float EPS_CLIP   = 1e-7f;

// ---- scratch (device globals: allocation-free per harness rules) ----
__device__ __align__(128) __half g_x16[B_ * D_];
__device__ __align__(128) __half g_w16[(size_t)D_ * V_];
__device__ float g_wpart[4][V_];   // partial column sum-of-squares (one per d-group)
__device__ float g_inv_x[B_];
__device__ float g_sumexp[B_];
__device__ float g_label_logit[B_];
__device__ int   g_labels[B_];

// ============================================================
// x prep: float4 loads, fp16 convert + row inv-norms; zero g_sumexp.
// Block 0 additionally normalizes labels (int64 vs int32 detection).
// ============================================================
__global__ void k_prep_x(const float* __restrict__ x, const int* __restrict__ raw) {
    int b = blockIdx.x;
    int t = threadIdx.x;  // 128

    if (b == 0) {
        __shared__ int nonzero;
        if (t == 0) nonzero = 0;
        __syncthreads();
        for (int i = t; i < 512; i += 128)
            if (raw[2 * i + 1] != 0) atomicOr(&nonzero, 1);
        __syncthreads();
        bool is64 = (nonzero == 0);
        for (int i = t; i < B_; i += 128)
            g_labels[i] = is64 ? raw[2 * i] : raw[i];
    }

    float4 v4 = *reinterpret_cast<const float4*>(&x[b * D_ + t * 4]);
    float ss = v4.x * v4.x + v4.y * v4.y + v4.z * v4.z + v4.w * v4.w;
    __half2 h01 = __floats2half2_rn(v4.x, v4.y);
    __half2 h23 = __floats2half2_rn(v4.z, v4.w);
    uint2 packed = make_uint2(*reinterpret_cast<uint32_t*>(&h01),
                              *reinterpret_cast<uint32_t*>(&h23));
    *reinterpret_cast<uint2*>(&g_x16[b * D_ + t * 4]) = packed;

#pragma unroll
    for (int o = 16; o; o >>= 1) ss += __shfl_xor_sync(0xffffffffu, ss, o);
    __shared__ float ws[4];
    if ((t & 31) == 0) ws[t >> 5] = ss;
    __syncthreads();
    if (t == 0) {
        float s = ws[0] + ws[1] + ws[2] + ws[3];
        g_inv_x[b]  = 1.0f / fmaxf(sqrtf(s), 1e-12f);
        g_sumexp[b] = 0.f;
    }
}

// ============================================================
// w prep (2D, chip-saturating): fp16 convert + PARTIAL column sumsq
// grid = (ceil(V/256), 4) = 1564 CTAs; dg covers d in [dg*128, dg*128+128)
// ============================================================
__global__ void k_prep_w(const float* __restrict__ w) {
    int v = blockIdx.x * 256 + threadIdx.x;
    int dg = blockIdx.y;
    if (v >= V_) return;
    float ss = 0.f;
    size_t idx = (size_t)(dg * 128) * V_ + v;
#pragma unroll 8
    for (int d = 0; d < 128; d++) {
        float val = w[idx];
        ss += val * val;
        g_w16[idx] = __float2half(val);
        idx += V_;
    }
    g_wpart[dg][v] = ss;
}

// ============================================================
// Persistent GEMM + fused ArcFace epilogue  (fp16 in, fp16 accum)
// 296 CTAs (2/SM), each loops tiles t = cta, cta+296, ... < 3128
// tile: bm = t % 8, bn = t / 8  (B-sharing tiles concurrent -> L2 reuse)
// CTA tile: BM=128 x BN=256, BK=32, 512 threads (2x8 warps, 64x32/warp)
// ============================================================
#define BM 128
#define BN 256
#define BK 32
#define STAGES 3
#define A_PITCH 40    // 32 + 8 pad (80B rows; conflict-free ldmatrix)
#define B_PITCH 264   // 256 + 8 pad (528B rows; conflict-free ldmatrix)
#define A_STAGE (BM * A_PITCH)          // halves = 5120
#define B_STAGE (BK * B_PITCH)          // 8448
#define SMEM_DYN ((A_STAGE + B_STAGE) * STAGES * 2)  // 81408 bytes
#define NCTA 296
#define NTILES (8 * 391)                // 3128

__device__ __forceinline__ void cp_async16(uint32_t smem, const void* gmem, int sz) {
    asm volatile("cp.async.cg.shared.global [%0], [%1], 16, %2;\n"
                 :: "r"(smem), "l"(gmem), "r"(sz) : "memory");
}
__device__ __forceinline__ void ldsm_x4(uint32_t& r0, uint32_t& r1, uint32_t& r2, uint32_t& r3, uint32_t addr) {
    asm volatile("ldmatrix.sync.aligned.m8n8.x4.shared.b16 {%0,%1,%2,%3}, [%4];\n"
                 : "=r"(r0), "=r"(r1), "=r"(r2), "=r"(r3) : "r"(addr));
}
__device__ __forceinline__ void ldsm_x4_t(uint32_t& r0, uint32_t& r1, uint32_t& r2, uint32_t& r3, uint32_t addr) {
    asm volatile("ldmatrix.sync.aligned.m8n8.x4.trans.shared.b16 {%0,%1,%2,%3}, [%4];\n"
                 : "=r"(r0), "=r"(r1), "=r"(r2), "=r"(r3) : "r"(addr));
}
__device__ __forceinline__ void mma16816_f16(uint32_t* c, const uint32_t* a, const uint32_t* b) {
    asm volatile(
        "mma.sync.aligned.m16n8k16.row.col.f16.f16.f16.f16 "
        "{%0,%1}, {%2,%3,%4,%5}, {%6,%7}, {%0,%1};\n"
        : "+r"(c[0]), "+r"(c[1])
        : "r"(a[0]), "r"(a[1]), "r"(a[2]), "r"(a[3]), "r"(b[0]), "r"(b[1]));
}

__global__ __launch_bounds__(512, 2) void k_gemm() {
    extern __shared__ __half smem_dyn[];
    __half* As = smem_dyn;                       // STAGES * A_STAGE
    __half* Bs = smem_dyn + STAGES * A_STAGE;    // STAGES * B_STAGE
    __shared__ float rowsum_sm[BM];
    __shared__ float inv_x_s[BM];
    __shared__ float inv_w_s[BN];
    __shared__ int   label_s[BM];

    const int tid = threadIdx.x;
    const int warp = tid >> 5, lane = tid & 31;
    const int wm = warp & 1;     // 2 warps over M (64 rows each)
    const int wn = warp >> 1;    // 8 warps over N (32 cols each)

    const uint32_t as0 = (uint32_t)__cvta_generic_to_shared(As);
    const uint32_t bs0 = (uint32_t)__cvta_generic_to_shared(Bs);

    for (int tile = blockIdx.x; tile < NTILES; tile += NCTA) {
        const int bm = tile & 7;
        const int bn = tile >> 3;

        auto load_tiles = [&](int kt, int buf) {
            {
                int row  = tid >> 2;             // 0..127
                int koff = (tid & 3) * 8;        // 0,8,16,24
                const __half* gp = &g_x16[(bm * BM + row) * D_ + kt * BK + koff];
                cp_async16(as0 + (buf * A_STAGE + row * A_PITCH + koff) * 2, gp, 16);
            }
#pragma unroll
            for (int i = 0; i < 2; i++) {
                int c = tid + i * 512;           // 0..1023
                int drow = c >> 5;               // 0..31
                int voff = (c & 31) * 8;         // 0..248
                int v = bn * BN + voff;
                const __half* gp = &g_w16[(size_t)(kt * BK + drow) * V_ + v];
                cp_async16(bs0 + (buf * B_STAGE + drow * B_PITCH + voff) * 2, gp, (v < V_) ? 16 : 0);
            }
            asm volatile("cp.async.commit_group;\n" ::: "memory");
        };

        load_tiles(0, 0);
        load_tiles(1, 1);

        if (tid < BM) {
            inv_x_s[tid]   = g_inv_x[bm * BM + tid];
            label_s[tid]   = g_labels[bm * BM + tid];
            rowsum_sm[tid] = 0.f;
        }
        if (tid < BN) {
            int v = bn * BN + tid;
            float s = 0.f;
            if (v < V_)
                s = g_wpart[0][v] + g_wpart[1][v] + g_wpart[2][v] + g_wpart[3][v];
            inv_w_s[tid] = (v < V_) ? 1.0f / fmaxf(sqrtf(s), 1e-12f) : 0.f;
        }

        uint32_t acc[4][4][2];  // fp16 accumulators (half2 pairs)
#pragma unroll
        for (int mf = 0; mf < 4; mf++)
#pragma unroll
            for (int nf = 0; nf < 4; nf++) {
                acc[mf][nf][0] = 0u;
                acc[mf][nf][1] = 0u;
            }

        const int KT = D_ / BK;  // 16
        for (int kt = 0; kt < KT; kt++) {
            asm volatile("cp.async.wait_group 1;\n" ::: "memory");
            __syncthreads();
            if (kt + 2 < KT) load_tiles(kt + 2, (kt + 2) % STAGES);
            else asm volatile("cp.async.commit_group;\n" ::: "memory");  // uniform group count

            int buf = kt % STAGES;
            uint32_t abase = as0 + buf * (A_STAGE * 2);
            uint32_t bbase = bs0 + buf * (B_STAGE * 2);

#pragma unroll
            for (int ks = 0; ks < 2; ks++) {
                uint32_t a[4][4];
#pragma unroll
                for (int mf = 0; mf < 4; mf++) {
                    int row = wm * 64 + mf * 16 + (lane & 15);
                    int col = ks * 16 + (lane >> 4) * 8;
                    ldsm_x4(a[mf][0], a[mf][1], a[mf][2], a[mf][3],
                            abase + (row * A_PITCH + col) * 2);
                }
                uint32_t b[4][2];
#pragma unroll
                for (int ng = 0; ng < 2; ng++) {
                    int krow = ks * 16 + (lane & 15);
                    int ncol = wn * 32 + ng * 16 + (lane >> 4) * 8;
                    uint32_t r0, r1, r2, r3;
                    ldsm_x4_t(r0, r1, r2, r3, bbase + (krow * B_PITCH + ncol) * 2);
                    b[ng * 2][0] = r0;      b[ng * 2][1] = r1;
                    b[ng * 2 + 1][0] = r2;  b[ng * 2 + 1][1] = r3;
                }
#pragma unroll
                for (int mf = 0; mf < 4; mf++)
#pragma unroll
                    for (int nf = 0; nf < 4; nf++)
                        mma16816_f16(acc[mf][nf], a[mf], b[nf]);
            }
        }
        __syncthreads();  // compute done; rowsum_sm zeros visible

        // ---- fused ArcFace epilogue ----
#pragma unroll
        for (int mf = 0; mf < 4; mf++) {
            float rs0 = 0.f, rs1 = 0.f;
            int r0 = wm * 64 + mf * 16 + (lane >> 2);
            int r1 = r0 + 8;
#pragma unroll
            for (int nf = 0; nf < 4; nf++) {
                int cbase = wn * 32 + nf * 8 + (lane & 3) * 2;
                float2 v0 = __half22float2(*reinterpret_cast<__half2*>(&acc[mf][nf][0]));  // row r0
                float2 v1 = __half22float2(*reinterpret_cast<__half2*>(&acc[mf][nf][1]));  // row r1
                float d0[2] = {v0.x, v0.y};
                float d1[2] = {v1.x, v1.y};
#pragma unroll
                for (int j = 0; j < 2; j++) {
                    int cc = cbase + j;
                    int v = bn * BN + cc;
                    if (v < V_) {
                        {
                            float cv = d0[j] * inv_x_s[r0] * inv_w_s[cc];
                            cv = fminf(fmaxf(cv, -1.f + EPS_CLIP), 1.f - EPS_CLIP);
                            float lg;
                            if (label_s[r0] == v) {
                                float s = sqrtf(fmaxf(1.f - cv * cv, 0.f));
                                lg = cv * MARGIN_COS - s * MARGIN_SIN;
                                g_label_logit[bm * BM + r0] = lg;
                            } else lg = cv;
                            rs0 += __expf(lg);
                        }
                        {
                            float cv = d1[j] * inv_x_s[r1] * inv_w_s[cc];
                            cv = fminf(fmaxf(cv, -1.f + EPS_CLIP), 1.f - EPS_CLIP);
                            float lg;
                            if (label_s[r1] == v) {
                                float s = sqrtf(fmaxf(1.f - cv * cv, 0.f));
                                lg = cv * MARGIN_COS - s * MARGIN_SIN;
                                g_label_logit[bm * BM + r1] = lg;
                            } else lg = cv;
                            rs1 += __expf(lg);
                        }
                    }
                }
            }
            rs0 += __shfl_xor_sync(0xffffffffu, rs0, 1);
            rs0 += __shfl_xor_sync(0xffffffffu, rs0, 2);
            rs1 += __shfl_xor_sync(0xffffffffu, rs1, 1);
            rs1 += __shfl_xor_sync(0xffffffffu, rs1, 2);
            if ((lane & 3) == 0) {
                atomicAdd(&rowsum_sm[r0], rs0);
                atomicAdd(&rowsum_sm[r1], rs1);
            }
        }
        __syncthreads();
        if (tid < BM) atomicAdd(&g_sumexp[bm * BM + tid], rowsum_sm[tid]);
        __syncthreads();  // rowsum_sm reused next tile
    }
}

// ============================================================
// final: loss = mean_b( log(sumexp[b]) - label_logit[b] )
// ============================================================
__global__ void k_final(float* __restrict__ out) {
    int t = threadIdx.x;  // 1024
    float v = logf(g_sumexp[t]) - g_label_logit[t];
#pragma unroll
    for (int o = 16; o; o >>= 1) v += __shfl_xor_sync(0xffffffffu, v, o);
    __shared__ float ws[32];
    if ((t & 31) == 0) ws[t >> 5] = v;
    __syncthreads();
    if (t < 32) {
        float s = ws[t];
#pragma unroll
        for (int o = 16; o; o >>= 1) s += __shfl_xor_sync(0xffffffffu, s, o);
        if (t == 0) out[0] = s * (1.0f / (float)B_);
    }
}

// ============================================================
extern "C" void kernel_launch(void* const* d_in, const int* in_sizes, int n_in,
                              void* d_out, int out_size) {
    const float* x = (const float*)d_in[0];
    const float* w = (const float*)d_in[1];
    const int*   labels_raw = (const int*)d_in[2];
    float* out = (float*)d_out;

    static bool attr_set = false;
    if (!attr_set) {
        cudaFuncSetAttribute(k_gemm, cudaFuncAttributeMaxDynamicSharedMemorySize, SMEM_DYN);
        attr_set = true;
    }

    dim3 pgrid((V_ + 255) / 256, 4);   // 1564 CTAs, chip-saturating
    k_prep_w<<<pgrid, 256>>>(w);
    k_prep_x<<<B_, 128>>>(x, labels_raw);
    k_gemm<<<NCTA, 512, SMEM_DYN>>>();  // persistent: 2 CTAs/SM, no wave tail
    k_final<<<1, 1024>>>(out);
}